// round 1
// baseline (speedup 1.0000x reference)
#include <cuda_runtime.h>
#include <cuda_bf16.h>
#include <math.h>

// Problem constants
#define Bn 8
#define Cn 256
#define Nn 4096   // 64*64

// Scratch: 3 projected tensors stored transposed [B, N, C] (q, k, v), and
// the score matrix [B, N, N]. __device__ globals per harness rules.
__device__ float g_qkvT[(size_t)3 * Bn * Nn * Cn];          // 96 MB
__device__ float g_S[(size_t)Bn * Nn * Nn];                 // 512 MB

#define QKV_STRIDE ((size_t)Bn * Nn * Cn)

// ---------------------------------------------------------------------------
// Kernel 1: 1x1 conv projection.
// outT[b, n, o] = sum_c W[o, c] * x[b, c, n] + bias[o]
// Tile: 64(n) x 64(o), k-chunk 16 over c. Block 16x16, 4x4 micro-tile.
// ---------------------------------------------------------------------------
__global__ void proj_kernel(const float* __restrict__ x,
                            const float* __restrict__ W,
                            const float* __restrict__ bias,
                            int which) {
    __shared__ __align__(16) float As[16][64];  // As[cc][nn] = x[c0+cc, n0+nn]
    __shared__ __align__(16) float Bs[16][64];  // Bs[cc][oo] = W[o0+oo, c0+cc]

    const int b  = blockIdx.z;
    const int o0 = blockIdx.y * 64;
    const int n0 = blockIdx.x * 64;
    const int tx = threadIdx.x, ty = threadIdx.y;
    const int tid = ty * 16 + tx;

    const float* xb = x + (size_t)b * Cn * Nn;

    float acc[4][4] = {};

    for (int c0 = 0; c0 < Cn; c0 += 16) {
        #pragma unroll
        for (int t = 0; t < 4; t++) {
            int idx = tid + t * 256;
            int cc = idx >> 6;    // /64
            int nn = idx & 63;
            As[cc][nn] = xb[(size_t)(c0 + cc) * Nn + n0 + nn];
        }
        #pragma unroll
        for (int t = 0; t < 4; t++) {
            int idx = tid + t * 256;
            int cc = idx & 15;
            int oo = idx >> 4;
            Bs[cc][oo] = W[(size_t)(o0 + oo) * Cn + c0 + cc];
        }
        __syncthreads();

        #pragma unroll
        for (int cc = 0; cc < 16; cc++) {
            float4 av = *reinterpret_cast<const float4*>(&As[cc][ty * 4]);
            float4 bv = *reinterpret_cast<const float4*>(&Bs[cc][tx * 4]);
            float a[4] = {av.x, av.y, av.z, av.w};
            float bb[4] = {bv.x, bv.y, bv.z, bv.w};
            #pragma unroll
            for (int i = 0; i < 4; i++)
                #pragma unroll
                for (int j = 0; j < 4; j++)
                    acc[i][j] += a[i] * bb[j];
        }
        __syncthreads();
    }

    float* outT = g_qkvT + (size_t)which * QKV_STRIDE + (size_t)b * Nn * Cn;
    #pragma unroll
    for (int i = 0; i < 4; i++) {
        int n = n0 + ty * 4 + i;
        #pragma unroll
        for (int j = 0; j < 4; j++) {
            int o = o0 + tx * 4 + j;
            outT[(size_t)n * Cn + o] = acc[i][j] + bias[o];
        }
    }
}

// ---------------------------------------------------------------------------
// Kernel 2: scores. S[b, i, j] = mask[b, i] * sum_c qT[b,i,c] * kT[b,j,c]
// Tile 64(i) x 64(j), k-chunk 16 over c (16 iterations).
// ---------------------------------------------------------------------------
__global__ void scores_kernel(const float* __restrict__ mask) {
    __shared__ __align__(16) float As[16][64];  // As[cc][ii]
    __shared__ __align__(16) float Bs[16][64];  // Bs[cc][jj]

    const int b  = blockIdx.z;
    const int i0 = blockIdx.y * 64;
    const int j0 = blockIdx.x * 64;
    const int tx = threadIdx.x, ty = threadIdx.y;
    const int tid = ty * 16 + tx;

    const float* qb = g_qkvT + (size_t)b * Nn * Cn;                 // which=0
    const float* kb = g_qkvT + QKV_STRIDE + (size_t)b * Nn * Cn;    // which=1

    float acc[4][4] = {};

    for (int c0 = 0; c0 < Cn; c0 += 16) {
        #pragma unroll
        for (int t = 0; t < 4; t++) {
            int idx = tid + t * 256;
            int cc = idx & 15;
            int rr = idx >> 4;
            As[cc][rr] = qb[(size_t)(i0 + rr) * Cn + c0 + cc];
            Bs[cc][rr] = kb[(size_t)(j0 + rr) * Cn + c0 + cc];
        }
        __syncthreads();

        #pragma unroll
        for (int cc = 0; cc < 16; cc++) {
            float4 av = *reinterpret_cast<const float4*>(&As[cc][ty * 4]);
            float4 bv = *reinterpret_cast<const float4*>(&Bs[cc][tx * 4]);
            float a[4] = {av.x, av.y, av.z, av.w};
            float bb[4] = {bv.x, bv.y, bv.z, bv.w};
            #pragma unroll
            for (int i = 0; i < 4; i++)
                #pragma unroll
                for (int j = 0; j < 4; j++)
                    acc[i][j] += a[i] * bb[j];
        }
        __syncthreads();
    }

    float* Sb = g_S + (size_t)b * Nn * Nn;
    #pragma unroll
    for (int i = 0; i < 4; i++) {
        int ii = i0 + ty * 4 + i;
        float m = mask[(size_t)b * Nn + ii];
        float4 st;
        st.x = acc[i][0] * m;
        st.y = acc[i][1] * m;
        st.z = acc[i][2] * m;
        st.w = acc[i][3] * m;
        *reinterpret_cast<float4*>(&Sb[(size_t)ii * Nn + j0 + tx * 4]) = st;
    }
}

// ---------------------------------------------------------------------------
// Kernel 3: row softmax over S. One block (256 threads) per row of 4096.
// ---------------------------------------------------------------------------
__global__ void softmax_kernel() {
    float* row = g_S + (size_t)blockIdx.x * Nn;
    const int tid  = threadIdx.x;
    const int warp = tid >> 5;
    const int lane = tid & 31;

    __shared__ float sred[8];
    __shared__ float sbcast;

    float v[16];
    float mx = -1e30f;
    #pragma unroll
    for (int t = 0; t < 16; t++) {
        v[t] = row[tid + t * 256];
        mx = fmaxf(mx, v[t]);
    }
    #pragma unroll
    for (int o = 16; o > 0; o >>= 1)
        mx = fmaxf(mx, __shfl_xor_sync(0xffffffffu, mx, o));
    if (lane == 0) sred[warp] = mx;
    __syncthreads();
    if (warp == 0) {
        float x = sred[lane & 7];
        #pragma unroll
        for (int o = 4; o > 0; o >>= 1)
            x = fmaxf(x, __shfl_xor_sync(0xffffffffu, x, o));
        if (lane == 0) sbcast = x;
    }
    __syncthreads();
    mx = sbcast;

    float s = 0.f;
    #pragma unroll
    for (int t = 0; t < 16; t++) {
        v[t] = __expf(v[t] - mx);
        s += v[t];
    }
    #pragma unroll
    for (int o = 16; o > 0; o >>= 1)
        s += __shfl_xor_sync(0xffffffffu, s, o);
    __syncthreads();   // sred reuse guard
    if (lane == 0) sred[warp] = s;
    __syncthreads();
    if (warp == 0) {
        float x = sred[lane & 7];
        #pragma unroll
        for (int o = 4; o > 0; o >>= 1)
            x += __shfl_xor_sync(0xffffffffu, x, o);
        if (lane == 0) sbcast = x;
    }
    __syncthreads();
    float inv = 1.f / sbcast;

    #pragma unroll
    for (int t = 0; t < 16; t++)
        row[tid + t * 256] = v[t] * inv;
}

// ---------------------------------------------------------------------------
// Kernel 4: attn = P @ vT, then out = queries*mask + (1-mask)*attn.
// O[q, c] = sum_j P[b, q, j] * vT[b, j, c]; output written as [B, C, N].
// Tile 64(q) x 64(c), k-chunk 16 over j (256 iterations).
// ---------------------------------------------------------------------------
__global__ void pv_kernel(const float* __restrict__ mask,
                          const float* __restrict__ queries,
                          float* __restrict__ out) {
    __shared__ __align__(16) float As[16][64];   // As[jj][qq]
    __shared__ __align__(16) float Bs[16][64];   // Bs[jj][cc]
    __shared__ float So[64][65];                 // staged O tile [q][c]

    const int b  = blockIdx.z;
    const int c0 = blockIdx.y * 64;
    const int q0 = blockIdx.x * 64;
    const int tx = threadIdx.x, ty = threadIdx.y;
    const int tid = ty * 16 + tx;

    const float* Pb = g_S + (size_t)b * Nn * Nn;
    const float* vb = g_qkvT + 2 * QKV_STRIDE + (size_t)b * Nn * Cn;  // which=2

    float acc[4][4] = {};

    for (int j0 = 0; j0 < Nn; j0 += 16) {
        #pragma unroll
        for (int t = 0; t < 4; t++) {
            int idx = tid + t * 256;
            int jj = idx & 15;
            int qq = idx >> 4;
            As[jj][qq] = Pb[(size_t)(q0 + qq) * Nn + j0 + jj];
        }
        #pragma unroll
        for (int t = 0; t < 4; t++) {
            int idx = tid + t * 256;
            int cc = idx & 63;
            int jj = idx >> 6;
            Bs[jj][cc] = vb[(size_t)(j0 + jj) * Cn + c0 + cc];
        }
        __syncthreads();

        #pragma unroll
        for (int jj = 0; jj < 16; jj++) {
            float4 av = *reinterpret_cast<const float4*>(&As[jj][ty * 4]);
            float4 bv = *reinterpret_cast<const float4*>(&Bs[jj][tx * 4]);
            float a[4] = {av.x, av.y, av.z, av.w};
            float bb[4] = {bv.x, bv.y, bv.z, bv.w};
            #pragma unroll
            for (int i = 0; i < 4; i++)
                #pragma unroll
                for (int j = 0; j < 4; j++)
                    acc[i][j] += a[i] * bb[j];
        }
        __syncthreads();
    }

    // Stage O tile to smem for transposed coalesced output writes.
    #pragma unroll
    for (int i = 0; i < 4; i++)
        #pragma unroll
        for (int j = 0; j < 4; j++)
            So[ty * 4 + i][tx * 4 + j] = acc[i][j];
    __syncthreads();

    const int qq = tid & 63;
    const float m  = mask[(size_t)b * Nn + q0 + qq];
    const float om = 1.f - m;
    for (int cc = (tid >> 6); cc < 64; cc += 4) {
        size_t gi = (size_t)b * Cn * Nn + (size_t)(c0 + cc) * Nn + q0 + qq;
        out[gi] = queries[gi] * m + om * So[qq][cc];
    }
}

// ---------------------------------------------------------------------------
// Launch
// ---------------------------------------------------------------------------
extern "C" void kernel_launch(void* const* d_in, const int* in_sizes, int n_in,
                              void* d_out, int out_size) {
    const float* queries = (const float*)d_in[0];
    const float* keys    = (const float*)d_in[1];
    const float* mask    = (const float*)d_in[2];
    const float* Wq      = (const float*)d_in[3];
    const float* bq      = (const float*)d_in[4];
    const float* Wk      = (const float*)d_in[5];
    const float* bk      = (const float*)d_in[6];
    const float* Wv      = (const float*)d_in[7];
    const float* bv      = (const float*)d_in[8];
    float* out = (float*)d_out;

    dim3 blk(16, 16);

    // Projections: q from queries, k/v from keys.
    dim3 gproj(Nn / 64, Cn / 64, Bn);
    proj_kernel<<<gproj, blk>>>(queries, Wq, bq, 0);
    proj_kernel<<<gproj, blk>>>(keys,    Wk, bk, 1);
    proj_kernel<<<gproj, blk>>>(keys,    Wv, bv, 2);

    // Scores (QK^T * row mask).
    dim3 gsc(Nn / 64, Nn / 64, Bn);
    scores_kernel<<<gsc, blk>>>(mask);

    // Row softmax.
    softmax_kernel<<<Bn * Nn, 256>>>();

    // PV + final combine.
    dim3 gpv(Nn / 64, Cn / 64, Bn);
    pv_kernel<<<gpv, blk>>>(mask, queries, out);
}

// round 2
// speedup vs baseline: 1.1297x; 1.1297x over previous
#include <cuda_runtime.h>
#include <cuda_bf16.h>
#include <math.h>

// Problem constants
#define Bn 8
#define Cn 256
#define Nn 4096   // 64*64

// Scratch: projected q/k/v stored transposed [B, N, C], score matrix [B, N, N].
__device__ float g_qkvT[(size_t)3 * Bn * Nn * Cn];          // 96 MB
__device__ float g_S[(size_t)Bn * Nn * Nn];                 // 512 MB

#define QKV_STRIDE ((size_t)Bn * Nn * Cn)
#define TPAD 132   // padded stride for transposed smem tiles

// ---------------------------------------------------------------------------
// Kernel 1: 1x1 conv projection.  outT[b,n,o] = sum_c W[o,c]*x[b,c,n] + bias[o]
// 128(n) x 128(o) tile, k-chunk 16 over c, 256 threads, 8x8 micro-tile.
// ---------------------------------------------------------------------------
__global__ void __launch_bounds__(256, 2)
proj_kernel(const float* __restrict__ x,
            const float* __restrict__ W,
            const float* __restrict__ bias,
            int which) {
    __shared__ __align__(16) float As[16][128];   // As[cc][nn] = x[c0+cc, n0+nn]
    __shared__ __align__(16) float Bs[16][TPAD];  // Bs[cc][oo] = W[o0+oo, c0+cc]

    const int b  = blockIdx.z;
    const int o0 = blockIdx.y * 128;
    const int n0 = blockIdx.x * 128;
    const int tid = threadIdx.x;
    const int tx = tid & 15, ty = tid >> 4;

    const float* xb = x + (size_t)b * Cn * Nn;

    float acc[8][8] = {};

    for (int c0 = 0; c0 < Cn; c0 += 16) {
        // As: 16 x 128 direct (contiguous in n)
        #pragma unroll
        for (int k = 0; k < 2; k++) {
            int p = tid + k * 256;
            int cc = p >> 5, nn4 = (p & 31) * 4;
            float4 v = *reinterpret_cast<const float4*>(
                &xb[(size_t)(c0 + cc) * Nn + n0 + nn4]);
            *reinterpret_cast<float4*>(&As[cc][nn4]) = v;
        }
        // Bs: transpose-load W (contiguous in c)
        #pragma unroll
        for (int k = 0; k < 2; k++) {
            int p = tid + k * 256;
            int oo = p >> 2, c4 = (p & 3) * 4;
            float4 w = *reinterpret_cast<const float4*>(
                &W[(size_t)(o0 + oo) * Cn + c0 + c4]);
            Bs[c4 + 0][oo] = w.x;
            Bs[c4 + 1][oo] = w.y;
            Bs[c4 + 2][oo] = w.z;
            Bs[c4 + 3][oo] = w.w;
        }
        __syncthreads();

        #pragma unroll
        for (int cc = 0; cc < 16; cc++) {
            float4 a0 = *reinterpret_cast<const float4*>(&As[cc][ty * 8]);
            float4 a1 = *reinterpret_cast<const float4*>(&As[cc][ty * 8 + 4]);
            float4 b0 = *reinterpret_cast<const float4*>(&Bs[cc][tx * 8]);
            float4 b1 = *reinterpret_cast<const float4*>(&Bs[cc][tx * 8 + 4]);
            float a[8] = {a0.x, a0.y, a0.z, a0.w, a1.x, a1.y, a1.z, a1.w};
            float bb[8] = {b0.x, b0.y, b0.z, b0.w, b1.x, b1.y, b1.z, b1.w};
            #pragma unroll
            for (int i = 0; i < 8; i++)
                #pragma unroll
                for (int j = 0; j < 8; j++)
                    acc[i][j] += a[i] * bb[j];
        }
        __syncthreads();
    }

    float bj[8];
    #pragma unroll
    for (int j = 0; j < 8; j++) bj[j] = bias[o0 + tx * 8 + j];

    float* outT = g_qkvT + (size_t)which * QKV_STRIDE + (size_t)b * Nn * Cn;
    #pragma unroll
    for (int i = 0; i < 8; i++) {
        size_t base = (size_t)(n0 + ty * 8 + i) * Cn + o0 + tx * 8;
        float4 s0 = {acc[i][0] + bj[0], acc[i][1] + bj[1],
                     acc[i][2] + bj[2], acc[i][3] + bj[3]};
        float4 s1 = {acc[i][4] + bj[4], acc[i][5] + bj[5],
                     acc[i][6] + bj[6], acc[i][7] + bj[7]};
        *reinterpret_cast<float4*>(&outT[base])     = s0;
        *reinterpret_cast<float4*>(&outT[base + 4]) = s1;
    }
}

// ---------------------------------------------------------------------------
// Kernel 2: scores. S[b,i,j] = mask[b,i] * sum_c qT[b,i,c]*kT[b,j,c]
// 128(i) x 128(j) tile, K=256, k-chunk 16.
// ---------------------------------------------------------------------------
__global__ void __launch_bounds__(256, 2)
scores_kernel(const float* __restrict__ mask) {
    __shared__ __align__(16) float As[16][TPAD];  // As[cc][ii]
    __shared__ __align__(16) float Bs[16][TPAD];  // Bs[cc][jj]

    const int b  = blockIdx.z;
    const int i0 = blockIdx.y * 128;
    const int j0 = blockIdx.x * 128;
    const int tid = threadIdx.x;
    const int tx = tid & 15, ty = tid >> 4;

    const float* qb = g_qkvT + (size_t)b * Nn * Cn;
    const float* kb = g_qkvT + QKV_STRIDE + (size_t)b * Nn * Cn;

    float acc[8][8] = {};

    for (int c0 = 0; c0 < Cn; c0 += 16) {
        #pragma unroll
        for (int k = 0; k < 2; k++) {
            int p = tid + k * 256;
            int row = p >> 2, c4 = (p & 3) * 4;
            float4 qv = *reinterpret_cast<const float4*>(
                &qb[(size_t)(i0 + row) * Cn + c0 + c4]);
            float4 kv = *reinterpret_cast<const float4*>(
                &kb[(size_t)(j0 + row) * Cn + c0 + c4]);
            As[c4 + 0][row] = qv.x; As[c4 + 1][row] = qv.y;
            As[c4 + 2][row] = qv.z; As[c4 + 3][row] = qv.w;
            Bs[c4 + 0][row] = kv.x; Bs[c4 + 1][row] = kv.y;
            Bs[c4 + 2][row] = kv.z; Bs[c4 + 3][row] = kv.w;
        }
        __syncthreads();

        #pragma unroll
        for (int cc = 0; cc < 16; cc++) {
            float4 a0 = *reinterpret_cast<const float4*>(&As[cc][ty * 8]);
            float4 a1 = *reinterpret_cast<const float4*>(&As[cc][ty * 8 + 4]);
            float4 b0 = *reinterpret_cast<const float4*>(&Bs[cc][tx * 8]);
            float4 b1 = *reinterpret_cast<const float4*>(&Bs[cc][tx * 8 + 4]);
            float a[8] = {a0.x, a0.y, a0.z, a0.w, a1.x, a1.y, a1.z, a1.w};
            float bb[8] = {b0.x, b0.y, b0.z, b0.w, b1.x, b1.y, b1.z, b1.w};
            #pragma unroll
            for (int i = 0; i < 8; i++)
                #pragma unroll
                for (int j = 0; j < 8; j++)
                    acc[i][j] += a[i] * bb[j];
        }
        __syncthreads();
    }

    float* Sb = g_S + (size_t)b * Nn * Nn;
    #pragma unroll
    for (int i = 0; i < 8; i++) {
        int ii = i0 + ty * 8 + i;
        float m = mask[(size_t)b * Nn + ii];
        size_t base = (size_t)ii * Nn + j0 + tx * 8;
        float4 s0 = {acc[i][0] * m, acc[i][1] * m, acc[i][2] * m, acc[i][3] * m};
        float4 s1 = {acc[i][4] * m, acc[i][5] * m, acc[i][6] * m, acc[i][7] * m};
        *reinterpret_cast<float4*>(&Sb[base])     = s0;
        *reinterpret_cast<float4*>(&Sb[base + 4]) = s1;
    }
}

// ---------------------------------------------------------------------------
// Kernel 3: row softmax over S. One block (256 threads) per row of 4096.
// ---------------------------------------------------------------------------
__global__ void softmax_kernel() {
    float* row = g_S + (size_t)blockIdx.x * Nn;
    const int tid  = threadIdx.x;
    const int warp = tid >> 5;
    const int lane = tid & 31;

    __shared__ float sred[8];
    __shared__ float sbcast;

    float v[16];
    float mx = -1e30f;
    #pragma unroll
    for (int t = 0; t < 16; t++) {
        v[t] = row[tid + t * 256];
        mx = fmaxf(mx, v[t]);
    }
    #pragma unroll
    for (int o = 16; o > 0; o >>= 1)
        mx = fmaxf(mx, __shfl_xor_sync(0xffffffffu, mx, o));
    if (lane == 0) sred[warp] = mx;
    __syncthreads();
    if (warp == 0) {
        float x = sred[lane & 7];
        #pragma unroll
        for (int o = 4; o > 0; o >>= 1)
            x = fmaxf(x, __shfl_xor_sync(0xffffffffu, x, o));
        if (lane == 0) sbcast = x;
    }
    __syncthreads();
    mx = sbcast;

    float s = 0.f;
    #pragma unroll
    for (int t = 0; t < 16; t++) {
        v[t] = __expf(v[t] - mx);
        s += v[t];
    }
    #pragma unroll
    for (int o = 16; o > 0; o >>= 1)
        s += __shfl_xor_sync(0xffffffffu, s, o);
    __syncthreads();
    if (lane == 0) sred[warp] = s;
    __syncthreads();
    if (warp == 0) {
        float x = sred[lane & 7];
        #pragma unroll
        for (int o = 4; o > 0; o >>= 1)
            x += __shfl_xor_sync(0xffffffffu, x, o);
        if (lane == 0) sbcast = x;
    }
    __syncthreads();
    float inv = 1.f / sbcast;

    #pragma unroll
    for (int t = 0; t < 16; t++)
        row[tid + t * 256] = v[t] * inv;
}

// ---------------------------------------------------------------------------
// Kernel 4: attn = P @ vT, out = queries*mask + (1-mask)*attn, out is [B,C,N].
// Tile 128(q, tx dim) x 128(c, ty dim), K = N = 4096, k-chunk 16.
// Direct coalesced epilogue (thread's j-axis = q = contiguous output dim).
// ---------------------------------------------------------------------------
__global__ void __launch_bounds__(256, 2)
pv_kernel(const float* __restrict__ mask,
          const float* __restrict__ queries,
          float* __restrict__ out) {
    __shared__ __align__(16) float As[16][TPAD];  // As[jj][qq] = P[q0+qq, j0+jj]
    __shared__ __align__(16) float Bs[16][128];   // Bs[jj][cc] = v[j0+jj, c0+cc]

    const int b  = blockIdx.z;
    const int c0 = blockIdx.y * 128;
    const int q0 = blockIdx.x * 128;
    const int tid = threadIdx.x;
    const int tx = tid & 15, ty = tid >> 4;

    const float* Pb = g_S + (size_t)b * Nn * Nn;
    const float* vb = g_qkvT + 2 * QKV_STRIDE + (size_t)b * Nn * Cn;

    float acc[8][8] = {};   // acc[i = c][j = q]

    for (int j0 = 0; j0 < Nn; j0 += 16) {
        // As: transpose-load of P (contiguous in j within a q-row)
        #pragma unroll
        for (int k = 0; k < 2; k++) {
            int p = tid + k * 256;
            int qq = p >> 2, j4 = (p & 3) * 4;
            float4 pv = *reinterpret_cast<const float4*>(
                &Pb[(size_t)(q0 + qq) * Nn + j0 + j4]);
            As[j4 + 0][qq] = pv.x; As[j4 + 1][qq] = pv.y;
            As[j4 + 2][qq] = pv.z; As[j4 + 3][qq] = pv.w;
        }
        // Bs: direct load of v (contiguous in c)
        #pragma unroll
        for (int k = 0; k < 2; k++) {
            int p = tid + k * 256;
            int jj = p >> 5, c4 = (p & 31) * 4;
            float4 vv = *reinterpret_cast<const float4*>(
                &vb[(size_t)(j0 + jj) * Cn + c0 + c4]);
            *reinterpret_cast<float4*>(&Bs[jj][c4]) = vv;
        }
        __syncthreads();

        #pragma unroll
        for (int jj = 0; jj < 16; jj++) {
            float4 c0v = *reinterpret_cast<const float4*>(&Bs[jj][ty * 8]);
            float4 c1v = *reinterpret_cast<const float4*>(&Bs[jj][ty * 8 + 4]);
            float4 p0v = *reinterpret_cast<const float4*>(&As[jj][tx * 8]);
            float4 p1v = *reinterpret_cast<const float4*>(&As[jj][tx * 8 + 4]);
            float cv[8] = {c0v.x, c0v.y, c0v.z, c0v.w, c1v.x, c1v.y, c1v.z, c1v.w};
            float pv[8] = {p0v.x, p0v.y, p0v.z, p0v.w, p1v.x, p1v.y, p1v.z, p1v.w};
            #pragma unroll
            for (int i = 0; i < 8; i++)
                #pragma unroll
                for (int j = 0; j < 8; j++)
                    acc[i][j] += cv[i] * pv[j];
        }
        __syncthreads();
    }

    // Epilogue: out[b, c, q] = queries*m + (1-m)*attn, coalesced in q.
    float m[8];
    #pragma unroll
    for (int j = 0; j < 8; j++) m[j] = mask[(size_t)b * Nn + q0 + tx * 8 + j];

    #pragma unroll
    for (int i = 0; i < 8; i++) {
        int c = c0 + ty * 8 + i;
        size_t base = (size_t)b * Cn * Nn + (size_t)c * Nn + q0 + tx * 8;
        float4 qv0 = *reinterpret_cast<const float4*>(&queries[base]);
        float4 qv1 = *reinterpret_cast<const float4*>(&queries[base + 4]);
        float4 o0, o1;
        o0.x = qv0.x * m[0] + (1.f - m[0]) * acc[i][0];
        o0.y = qv0.y * m[1] + (1.f - m[1]) * acc[i][1];
        o0.z = qv0.z * m[2] + (1.f - m[2]) * acc[i][2];
        o0.w = qv0.w * m[3] + (1.f - m[3]) * acc[i][3];
        o1.x = qv1.x * m[4] + (1.f - m[4]) * acc[i][4];
        o1.y = qv1.y * m[5] + (1.f - m[5]) * acc[i][5];
        o1.z = qv1.z * m[6] + (1.f - m[6]) * acc[i][6];
        o1.w = qv1.w * m[7] + (1.f - m[7]) * acc[i][7];
        *reinterpret_cast<float4*>(&out[base])     = o0;
        *reinterpret_cast<float4*>(&out[base + 4]) = o1;
    }
}

// ---------------------------------------------------------------------------
// Launch
// ---------------------------------------------------------------------------
extern "C" void kernel_launch(void* const* d_in, const int* in_sizes, int n_in,
                              void* d_out, int out_size) {
    const float* queries = (const float*)d_in[0];
    const float* keys    = (const float*)d_in[1];
    const float* mask    = (const float*)d_in[2];
    const float* Wq      = (const float*)d_in[3];
    const float* bq      = (const float*)d_in[4];
    const float* Wk      = (const float*)d_in[5];
    const float* bk      = (const float*)d_in[6];
    const float* Wv      = (const float*)d_in[7];
    const float* bv      = (const float*)d_in[8];
    float* out = (float*)d_out;

    // Projections: q from queries, k/v from keys.
    dim3 gproj(Nn / 128, Cn / 128, Bn);
    proj_kernel<<<gproj, 256>>>(queries, Wq, bq, 0);
    proj_kernel<<<gproj, 256>>>(keys,    Wk, bk, 1);
    proj_kernel<<<gproj, 256>>>(keys,    Wv, bv, 2);

    // Scores (QK^T * row mask).
    dim3 gsc(Nn / 128, Nn / 128, Bn);
    scores_kernel<<<gsc, 256>>>(mask);

    // Row softmax.
    softmax_kernel<<<Bn * Nn, 256>>>();

    // PV + final combine.
    dim3 gpv(Nn / 128, Cn / 128, Bn);
    pv_kernel<<<gpv, 256>>>(mask, queries, out);
}

// round 4
// speedup vs baseline: 3.7817x; 3.3475x over previous
#include <cuda_runtime.h>
#include <cuda_bf16.h>
#include <cstdint>
#include <math.h>

// Problem constants
#define Bn 8
#define Cn 256
#define Nn 4096   // 64*64

// ---------------------------------------------------------------------------
// Scratch (device globals; no allocation allowed)
// ---------------------------------------------------------------------------
__device__ __nv_bfloat16 g_qh[(size_t)Bn * Nn * Cn];   // q hi  [B, N, C]
__device__ __nv_bfloat16 g_ql[(size_t)Bn * Nn * Cn];   // q lo
__device__ __nv_bfloat16 g_kh[(size_t)Bn * Nn * Cn];   // k hi  [B, N, C]
__device__ __nv_bfloat16 g_kl[(size_t)Bn * Nn * Cn];   // k lo
__device__ __nv_bfloat16 g_vh[(size_t)Bn * Cn * Nn];   // v hi  [B, C, N]
__device__ __nv_bfloat16 g_vl[(size_t)Bn * Cn * Nn];   // v lo
__device__ float         g_S [(size_t)Bn * Nn * Nn];   // scores fp32
__device__ __nv_bfloat16 g_Ph[(size_t)Bn * Nn * Nn];   // softmax hi [B, N, N]
__device__ __nv_bfloat16 g_Pl[(size_t)Bn * Nn * Nn];   // softmax lo

// ---------------------------------------------------------------------------
// Helpers: smem addr, swizzle, ldmatrix, mma, cp.async
// ---------------------------------------------------------------------------
__device__ __forceinline__ uint32_t smem_u32(const void* p) {
    uint32_t a;
    asm("{ .reg .u64 t; cvta.to.shared.u64 t, %1; cvt.u32.u64 %0, t; }"
        : "=r"(a) : "l"(p));
    return a;
}

#define SMEM_SWIZZLE_128B(off) ((off) ^ (((off) >> 3) & 0x70))

__device__ __forceinline__ void ldmx4(uint32_t* r, uint32_t a) {
    asm volatile("ldmatrix.sync.aligned.m8n8.x4.shared.b16 {%0,%1,%2,%3}, [%4];"
        : "=r"(r[0]), "=r"(r[1]), "=r"(r[2]), "=r"(r[3]) : "r"(a));
}

__device__ __forceinline__ void mma16816(float* d, const uint32_t* a,
                                         uint32_t b0, uint32_t b1) {
    asm volatile(
        "mma.sync.aligned.m16n8k16.row.col.f32.bf16.bf16.f32 "
        "{%0,%1,%2,%3}, {%4,%5,%6,%7}, {%8,%9}, {%0,%1,%2,%3};"
        : "+f"(d[0]), "+f"(d[1]), "+f"(d[2]), "+f"(d[3])
        : "r"(a[0]), "r"(a[1]), "r"(a[2]), "r"(a[3]), "r"(b0), "r"(b1));
}

// Copy one 128-row x 64-bf16 tile (128B rows, SW128 swizzle) via cp.async.
__device__ __forceinline__ void cp_tile(uint32_t sdst, const __nv_bfloat16* g,
                                        int rs, int tid) {
    #pragma unroll
    for (int t = 0; t < 4; t++) {
        int u = tid + t * 256;
        int row = u >> 3, q = u & 7;
        uint32_t d = sdst + SMEM_SWIZZLE_128B((uint32_t)(row * 128 + q * 16));
        const void* s = g + (size_t)row * rs + q * 8;
        asm volatile("cp.async.cg.shared.global [%0], [%1], 16;"
                     :: "r"(d), "l"(s));
    }
}

#define CP_COMMIT() asm volatile("cp.async.commit_group;" ::: "memory")
#define CP_WAIT1()  asm volatile("cp.async.wait_group 1;" ::: "memory")
#define CP_WAIT0()  asm volatile("cp.async.wait_group 0;" ::: "memory")

// SMEM: 2 stages x 4 tiles (Ah, Al, Bh, Bl) x 16KB
#define TILE_B   16384
#define STAGE_B  (4 * TILE_B)
#define MMA_SMEM (2 * STAGE_B)   // 128 KB

// ---------------------------------------------------------------------------
// Shared HMMA mainloop: acc[4][4][4] += A(128xK) @ B(128xK)^T with
// 2-way bf16 split (Ah*Bh + Ah*Bl + Al*Bh).  K consumed in chunks of 64.
// 8 warps: warp tile = 64(i) x 32(j); iBase=(wid>>2)*64, jBase=(wid&3)*32.
// ---------------------------------------------------------------------------
__device__ __forceinline__ void mma_mainloop(
    uint32_t sbase,
    const __nv_bfloat16* Ah, const __nv_bfloat16* Al,
    const __nv_bfloat16* Bh, const __nv_bfloat16* Bl,
    int rsA, int rsB, int nch,
    float acc[4][4][4], int tid, int wid, int lane)
{
    const int iBase = (wid >> 2) * 64;
    const int jBase = (wid & 3) * 32;
    const uint32_t lsw  = (uint32_t)((lane & 7) * 16);
    const uint32_t aoff = (uint32_t)((iBase + (lane & 15)) * 128 + (lane >> 4) * 16);
    const uint32_t boff = (uint32_t)((jBase + (lane & 15)) * 128 + (lane >> 4) * 16);

    // Prefetch chunk 0 into stage 0
    cp_tile(sbase + 0 * TILE_B, Ah, rsA, tid);
    cp_tile(sbase + 1 * TILE_B, Al, rsA, tid);
    cp_tile(sbase + 2 * TILE_B, Bh, rsB, tid);
    cp_tile(sbase + 3 * TILE_B, Bl, rsB, tid);
    CP_COMMIT();

    #pragma unroll 1
    for (int c = 0; c < nch; c++) {
        if (c + 1 < nch) {
            uint32_t st = sbase + ((c + 1) & 1) * STAGE_B;
            int ko = (c + 1) * 64;
            cp_tile(st + 0 * TILE_B, Ah + ko, rsA, tid);
            cp_tile(st + 1 * TILE_B, Al + ko, rsA, tid);
            cp_tile(st + 2 * TILE_B, Bh + ko, rsB, tid);
            cp_tile(st + 3 * TILE_B, Bl + ko, rsB, tid);
            CP_COMMIT();
            CP_WAIT1();
        } else {
            CP_WAIT0();
        }
        __syncthreads();

        uint32_t tb = sbase + (c & 1) * STAGE_B;
        #pragma unroll
        for (int ks = 0; ks < 4; ks++) {
            uint32_t kb = (uint32_t)(ks * 32);

            uint32_t ah[4][4], al[4][4];
            #pragma unroll
            for (int it = 0; it < 4; it++) {
                uint32_t o = (aoff + it * 2048 + kb) ^ lsw;
                ldmx4(ah[it], tb + o);
                ldmx4(al[it], tb + TILE_B + o);
            }
            uint32_t bh[4][2], bl[4][2];
            #pragma unroll
            for (int jp = 0; jp < 2; jp++) {
                uint32_t o = (boff + jp * 2048 + kb) ^ lsw;
                uint32_t t4[4];
                ldmx4(t4, tb + 2 * TILE_B + o);
                bh[jp * 2][0]     = t4[0]; bh[jp * 2][1]     = t4[2];
                bh[jp * 2 + 1][0] = t4[1]; bh[jp * 2 + 1][1] = t4[3];
                ldmx4(t4, tb + 3 * TILE_B + o);
                bl[jp * 2][0]     = t4[0]; bl[jp * 2][1]     = t4[2];
                bl[jp * 2 + 1][0] = t4[1]; bl[jp * 2 + 1][1] = t4[3];
            }

            #pragma unroll
            for (int it = 0; it < 4; it++)
                #pragma unroll
                for (int nt = 0; nt < 4; nt++) {
                    mma16816(acc[it][nt], ah[it], bh[nt][0], bh[nt][1]);
                    mma16816(acc[it][nt], ah[it], bl[nt][0], bl[nt][1]);
                    mma16816(acc[it][nt], al[it], bh[nt][0], bh[nt][1]);
                }
        }
        __syncthreads();
    }
}

// ---------------------------------------------------------------------------
// Kernel 1: 1x1 conv projection (SIMT fp32) -> bf16 hi/lo split outputs.
// vmode=0: out [N, C] (q, k).  vmode=1: out [C, N] (v).
// ---------------------------------------------------------------------------
__device__ __forceinline__ void store8_bf16_split(__nv_bfloat16* dh,
                                                  __nv_bfloat16* dl,
                                                  const float* f) {
    uint4 uh, ul;
    __nv_bfloat162* ph = reinterpret_cast<__nv_bfloat162*>(&uh);
    __nv_bfloat162* pl = reinterpret_cast<__nv_bfloat162*>(&ul);
    #pragma unroll
    for (int k = 0; k < 4; k++) {
        float a = f[2 * k], b = f[2 * k + 1];
        __nv_bfloat16 ah = __float2bfloat16_rn(a);
        __nv_bfloat16 bh = __float2bfloat16_rn(b);
        float al = a - __bfloat162float(ah);
        float bl = b - __bfloat162float(bh);
        ph[k] = __halves2bfloat162(ah, bh);
        pl[k] = __halves2bfloat162(__float2bfloat16_rn(al), __float2bfloat16_rn(bl));
    }
    *reinterpret_cast<uint4*>(dh) = uh;
    *reinterpret_cast<uint4*>(dl) = ul;
}

__global__ void __launch_bounds__(256, 2)
proj_kernel(const float* __restrict__ x,
            const float* __restrict__ W,
            const float* __restrict__ bias,
            __nv_bfloat16* __restrict__ oh,
            __nv_bfloat16* __restrict__ ol,
            int vmode) {
    __shared__ __align__(16) float As[16][128];   // As[cc][nn]
    __shared__ __align__(16) float Bs[16][132];   // Bs[cc][oo]

    const int b  = blockIdx.z;
    const int o0 = blockIdx.y * 128;
    const int n0 = blockIdx.x * 128;
    const int tid = threadIdx.x;
    const int tx = tid & 15, ty = tid >> 4;

    const float* xb = x + (size_t)b * Cn * Nn;

    float acc[8][8] = {};

    for (int c0 = 0; c0 < Cn; c0 += 16) {
        #pragma unroll
        for (int k = 0; k < 2; k++) {
            int p = tid + k * 256;
            int cc = p >> 5, nn4 = (p & 31) * 4;
            *reinterpret_cast<float4*>(&As[cc][nn4]) =
                *reinterpret_cast<const float4*>(&xb[(size_t)(c0 + cc) * Nn + n0 + nn4]);
        }
        #pragma unroll
        for (int k = 0; k < 2; k++) {
            int p = tid + k * 256;
            int oo = p >> 2, c4 = (p & 3) * 4;
            float4 w = *reinterpret_cast<const float4*>(&W[(size_t)(o0 + oo) * Cn + c0 + c4]);
            Bs[c4 + 0][oo] = w.x;
            Bs[c4 + 1][oo] = w.y;
            Bs[c4 + 2][oo] = w.z;
            Bs[c4 + 3][oo] = w.w;
        }
        __syncthreads();

        #pragma unroll
        for (int cc = 0; cc < 16; cc++) {
            float4 a0 = *reinterpret_cast<const float4*>(&As[cc][ty * 8]);
            float4 a1 = *reinterpret_cast<const float4*>(&As[cc][ty * 8 + 4]);
            float4 b0 = *reinterpret_cast<const float4*>(&Bs[cc][tx * 8]);
            float4 b1 = *reinterpret_cast<const float4*>(&Bs[cc][tx * 8 + 4]);
            float a[8] = {a0.x, a0.y, a0.z, a0.w, a1.x, a1.y, a1.z, a1.w};
            float bb[8] = {b0.x, b0.y, b0.z, b0.w, b1.x, b1.y, b1.z, b1.w};
            #pragma unroll
            for (int i = 0; i < 8; i++)
                #pragma unroll
                for (int j = 0; j < 8; j++)
                    acc[i][j] += a[i] * bb[j];
        }
        __syncthreads();
    }

    float bj[8];
    #pragma unroll
    for (int j = 0; j < 8; j++) bj[j] = bias[o0 + tx * 8 + j];

    if (!vmode) {
        __nv_bfloat16* dh = oh + (size_t)b * Nn * Cn;
        __nv_bfloat16* dl = ol + (size_t)b * Nn * Cn;
        #pragma unroll
        for (int i = 0; i < 8; i++) {
            float f[8];
            #pragma unroll
            for (int j = 0; j < 8; j++) f[j] = acc[i][j] + bj[j];
            size_t base = (size_t)(n0 + ty * 8 + i) * Cn + o0 + tx * 8;
            store8_bf16_split(dh + base, dl + base, f);
        }
    } else {
        __nv_bfloat16* dh = oh + (size_t)b * Cn * Nn;
        __nv_bfloat16* dl = ol + (size_t)b * Cn * Nn;
        #pragma unroll
        for (int j = 0; j < 8; j++) {
            float f[8];
            #pragma unroll
            for (int i = 0; i < 8; i++) f[i] = acc[i][j] + bj[j];
            size_t base = (size_t)(o0 + tx * 8 + j) * Nn + n0 + ty * 8;
            store8_bf16_split(dh + base, dl + base, f);
        }
    }
}

// ---------------------------------------------------------------------------
// Kernel 2: scores via HMMA.  S[b,i,j] = mask[b,i] * <q_i, k_j>
// ---------------------------------------------------------------------------
__global__ void __launch_bounds__(256, 1)
scores_mma(const float* __restrict__ mask) {
    extern __shared__ char smem[];
    uint32_t sbase = smem_u32(smem);
    const int tid = threadIdx.x;
    const int wid = tid >> 5, lane = tid & 31;

    const int b  = blockIdx.z;
    const int i0 = blockIdx.y * 128;
    const int j0 = blockIdx.x * 128;

    const __nv_bfloat16* Ah = g_qh + ((size_t)b * Nn + i0) * Cn;
    const __nv_bfloat16* Al = g_ql + ((size_t)b * Nn + i0) * Cn;
    const __nv_bfloat16* Bh = g_kh + ((size_t)b * Nn + j0) * Cn;
    const __nv_bfloat16* Bl = g_kl + ((size_t)b * Nn + j0) * Cn;

    float acc[4][4][4] = {};
    mma_mainloop(sbase, Ah, Al, Bh, Bl, Cn, Cn, Cn / 64, acc, tid, wid, lane);

    // Epilogue
    const int iBase = (wid >> 2) * 64;
    const int jBase = (wid & 3) * 32;
    const int g = lane >> 2, cp2 = (lane & 3) * 2;
    const float* mb = mask + (size_t)b * Nn;
    float* Sb = g_S + (size_t)b * Nn * Nn;

    #pragma unroll
    for (int it = 0; it < 4; it++) {
        int r1 = i0 + iBase + it * 16 + g;
        float m1 = mb[r1], m2 = mb[r1 + 8];
        #pragma unroll
        for (int nt = 0; nt < 4; nt++) {
            int cc = j0 + jBase + nt * 8 + cp2;
            float2 v1 = {acc[it][nt][0] * m1, acc[it][nt][1] * m1};
            float2 v2 = {acc[it][nt][2] * m2, acc[it][nt][3] * m2};
            *reinterpret_cast<float2*>(&Sb[(size_t)r1 * Nn + cc])       = v1;
            *reinterpret_cast<float2*>(&Sb[(size_t)(r1 + 8) * Nn + cc]) = v2;
        }
    }
}

// ---------------------------------------------------------------------------
// Kernel 3: row softmax over S; writes P as bf16 hi/lo.
// ---------------------------------------------------------------------------
__global__ void softmax_kernel() {
    const size_t row = blockIdx.x;
    const float* src = g_S + row * Nn;
    __nv_bfloat16* dh = g_Ph + row * Nn;
    __nv_bfloat16* dl = g_Pl + row * Nn;

    const int tid  = threadIdx.x;
    const int warp = tid >> 5;
    const int lane = tid & 31;

    __shared__ float sred[8];
    __shared__ float sbcast;

    float2 v[8];
    float mx = -1e30f;
    #pragma unroll
    for (int t = 0; t < 8; t++) {
        v[t] = *reinterpret_cast<const float2*>(&src[t * 512 + tid * 2]);
        mx = fmaxf(mx, fmaxf(v[t].x, v[t].y));
    }
    #pragma unroll
    for (int o = 16; o > 0; o >>= 1)
        mx = fmaxf(mx, __shfl_xor_sync(0xffffffffu, mx, o));
    if (lane == 0) sred[warp] = mx;
    __syncthreads();
    if (warp == 0) {
        float x = sred[lane & 7];
        #pragma unroll
        for (int o = 4; o > 0; o >>= 1)
            x = fmaxf(x, __shfl_xor_sync(0xffffffffu, x, o));
        if (lane == 0) sbcast = x;
    }
    __syncthreads();
    mx = sbcast;

    float s = 0.f;
    #pragma unroll
    for (int t = 0; t < 8; t++) {
        v[t].x = __expf(v[t].x - mx);
        v[t].y = __expf(v[t].y - mx);
        s += v[t].x + v[t].y;
    }
    #pragma unroll
    for (int o = 16; o > 0; o >>= 1)
        s += __shfl_xor_sync(0xffffffffu, s, o);
    __syncthreads();
    if (lane == 0) sred[warp] = s;
    __syncthreads();
    if (warp == 0) {
        float x = sred[lane & 7];
        #pragma unroll
        for (int o = 4; o > 0; o >>= 1)
            x += __shfl_xor_sync(0xffffffffu, x, o);
        if (lane == 0) sbcast = x;
    }
    __syncthreads();
    const float inv = 1.f / sbcast;

    #pragma unroll
    for (int t = 0; t < 8; t++) {
        float a = v[t].x * inv, b = v[t].y * inv;
        __nv_bfloat16 ah = __float2bfloat16_rn(a);
        __nv_bfloat16 bh = __float2bfloat16_rn(b);
        float al = a - __bfloat162float(ah);
        float bl = b - __bfloat162float(bh);
        int off = t * 512 + tid * 2;
        *reinterpret_cast<__nv_bfloat162*>(&dh[off]) = __halves2bfloat162(ah, bh);
        *reinterpret_cast<__nv_bfloat162*>(&dl[off]) =
            __halves2bfloat162(__float2bfloat16_rn(al), __float2bfloat16_rn(bl));
    }
}

// ---------------------------------------------------------------------------
// Kernel 4: PV via HMMA (computes D^T: rows = c, cols = q) + final blend.
// D[c][q] = sum_j v[c][j] * P[q][j];  out[b,c,q] = queries*m + (1-m)*D
// ---------------------------------------------------------------------------
__global__ void __launch_bounds__(256, 1)
pv_mma(const float* __restrict__ mask,
       const float* __restrict__ queries,
       float* __restrict__ out) {
    extern __shared__ char smem[];
    uint32_t sbase = smem_u32(smem);
    const int tid = threadIdx.x;
    const int wid = tid >> 5, lane = tid & 31;

    const int b  = blockIdx.z;
    const int c0 = blockIdx.y * 128;
    const int q0 = blockIdx.x * 128;

    const __nv_bfloat16* Ah = g_vh + ((size_t)b * Cn + c0) * Nn;
    const __nv_bfloat16* Al = g_vl + ((size_t)b * Cn + c0) * Nn;
    const __nv_bfloat16* Bh = g_Ph + ((size_t)b * Nn + q0) * Nn;
    const __nv_bfloat16* Bl = g_Pl + ((size_t)b * Nn + q0) * Nn;

    float acc[4][4][4] = {};
    mma_mainloop(sbase, Ah, Al, Bh, Bl, Nn, Nn, Nn / 64, acc, tid, wid, lane);

    // Epilogue: rows = c, cols = q (contiguous in output)
    const int iBase = (wid >> 2) * 64;
    const int jBase = (wid & 3) * 32;
    const int g = lane >> 2, cp2 = (lane & 3) * 2;
    const float* mb = mask + (size_t)b * Nn;

    int   qc[4];
    float m0[4], m1[4];
    #pragma unroll
    for (int nt = 0; nt < 4; nt++) {
        qc[nt] = q0 + jBase + nt * 8 + cp2;
        m0[nt] = mb[qc[nt]];
        m1[nt] = mb[qc[nt] + 1];
    }

    #pragma unroll
    for (int it = 0; it < 4; it++) {
        int cr = c0 + iBase + it * 16 + g;
        #pragma unroll
        for (int nt = 0; nt < 4; nt++) {
            size_t gi1 = ((size_t)b * Cn + cr) * Nn + qc[nt];
            size_t gi2 = gi1 + (size_t)8 * Nn;
            float2 qa = *reinterpret_cast<const float2*>(&queries[gi1]);
            float2 qb = *reinterpret_cast<const float2*>(&queries[gi2]);
            float2 o1, o2;
            o1.x = qa.x * m0[nt] + (1.f - m0[nt]) * acc[it][nt][0];
            o1.y = qa.y * m1[nt] + (1.f - m1[nt]) * acc[it][nt][1];
            o2.x = qb.x * m0[nt] + (1.f - m0[nt]) * acc[it][nt][2];
            o2.y = qb.y * m1[nt] + (1.f - m1[nt]) * acc[it][nt][3];
            *reinterpret_cast<float2*>(&out[gi1]) = o1;
            *reinterpret_cast<float2*>(&out[gi2]) = o2;
        }
    }
}

// ---------------------------------------------------------------------------
// Launch
// ---------------------------------------------------------------------------
extern "C" void kernel_launch(void* const* d_in, const int* in_sizes, int n_in,
                              void* d_out, int out_size) {
    const float* queries = (const float*)d_in[0];
    const float* keys    = (const float*)d_in[1];
    const float* mask    = (const float*)d_in[2];
    const float* Wq      = (const float*)d_in[3];
    const float* bq      = (const float*)d_in[4];
    const float* Wk      = (const float*)d_in[5];
    const float* bk      = (const float*)d_in[6];
    const float* Wv      = (const float*)d_in[7];
    const float* bv      = (const float*)d_in[8];
    float* out = (float*)d_out;

    cudaFuncSetAttribute(scores_mma, cudaFuncAttributeMaxDynamicSharedMemorySize,
                         MMA_SMEM);
    cudaFuncSetAttribute(pv_mma, cudaFuncAttributeMaxDynamicSharedMemorySize,
                         MMA_SMEM);

    __nv_bfloat16 *qh, *ql, *kh, *kl, *vh, *vl;
    cudaGetSymbolAddress((void**)&qh, g_qh);
    cudaGetSymbolAddress((void**)&ql, g_ql);
    cudaGetSymbolAddress((void**)&kh, g_kh);
    cudaGetSymbolAddress((void**)&kl, g_kl);
    cudaGetSymbolAddress((void**)&vh, g_vh);
    cudaGetSymbolAddress((void**)&vl, g_vl);

    // Projections (SIMT fp32 -> bf16 hi/lo split outputs)
    dim3 gproj(Nn / 128, Cn / 128, Bn);
    proj_kernel<<<gproj, 256>>>(queries, Wq, bq, qh, ql, 0);
    proj_kernel<<<gproj, 256>>>(keys,    Wk, bk, kh, kl, 0);
    proj_kernel<<<gproj, 256>>>(keys,    Wv, bv, vh, vl, 1);

    // Scores (HMMA, 3-product bf16 split) + mask
    dim3 gsc(Nn / 128, Nn / 128, Bn);
    scores_mma<<<gsc, 256, MMA_SMEM>>>(mask);

    // Row softmax -> P hi/lo
    softmax_kernel<<<Bn * Nn, 256>>>();

    // PV (HMMA, computes D^T) + final blend
    dim3 gpv(Nn / 128, Cn / 128, Bn);
    pv_mma<<<gpv, 256, MMA_SMEM>>>(mask, queries, out);
}

// round 5
// speedup vs baseline: 3.8855x; 1.0274x over previous
#include <cuda_runtime.h>
#include <cuda_bf16.h>
#include <cstdint>
#include <math.h>

// Problem constants
#define Bn 8
#define Cn 256
#define Nn 4096   // 64*64

// ---------------------------------------------------------------------------
// Scratch (device globals; no allocation allowed)
// ---------------------------------------------------------------------------
__device__ __nv_bfloat16 g_qh[(size_t)Bn * Nn * Cn];   // q hi  [B, N, C]
__device__ __nv_bfloat16 g_ql[(size_t)Bn * Nn * Cn];   // q lo
__device__ __nv_bfloat16 g_kh[(size_t)Bn * Nn * Cn];   // k hi  [B, N, C]
__device__ __nv_bfloat16 g_kl[(size_t)Bn * Nn * Cn];   // k lo
__device__ __nv_bfloat16 g_vh[(size_t)Bn * Cn * Nn];   // v hi  [B, C, N]
__device__ __nv_bfloat16 g_vl[(size_t)Bn * Cn * Nn];   // v lo
__device__ float         g_S [(size_t)Bn * Nn * Nn];   // scores fp32
__device__ __nv_bfloat16 g_Ph[(size_t)Bn * Nn * Nn];   // softmax hi [B, N, N]
__device__ __nv_bfloat16 g_Pl[(size_t)Bn * Nn * Nn];   // softmax lo

// ---------------------------------------------------------------------------
// Helpers
// ---------------------------------------------------------------------------
__device__ __forceinline__ uint32_t smem_u32(const void* p) {
    uint32_t a;
    asm("{ .reg .u64 t; cvta.to.shared.u64 t, %1; cvt.u32.u64 %0, t; }"
        : "=r"(a) : "l"(p));
    return a;
}

// SW64 swizzle for 64-byte rows: bits[5:4] ^= bits[8:7]
#define SMEM_SWIZZLE_64B(off) ((off) ^ (((off) >> 3) & 0x30))

__device__ __forceinline__ void ldmx4(uint32_t* r, uint32_t a) {
    asm volatile("ldmatrix.sync.aligned.m8n8.x4.shared.b16 {%0,%1,%2,%3}, [%4];"
        : "=r"(r[0]), "=r"(r[1]), "=r"(r[2]), "=r"(r[3]) : "r"(a));
}

__device__ __forceinline__ void mma16816(float* d, const uint32_t* a,
                                         uint32_t b0, uint32_t b1) {
    asm volatile(
        "mma.sync.aligned.m16n8k16.row.col.f32.bf16.bf16.f32 "
        "{%0,%1,%2,%3}, {%4,%5,%6,%7}, {%8,%9}, {%0,%1,%2,%3};"
        : "+f"(d[0]), "+f"(d[1]), "+f"(d[2]), "+f"(d[3])
        : "r"(a[0]), "r"(a[1]), "r"(a[2]), "r"(a[3]), "r"(b0), "r"(b1));
}

// Copy one 128-row x 32-bf16 tile (64B rows, SW64 swizzle) via cp.async.
__device__ __forceinline__ void cp_tile(uint32_t sdst, const __nv_bfloat16* g,
                                        int rs, int tid) {
    #pragma unroll
    for (int t = 0; t < 2; t++) {
        int u = tid + t * 256;          // 0..511 16B transfers
        int row = u >> 2, q = u & 3;
        uint32_t d = sdst + SMEM_SWIZZLE_64B((uint32_t)(row * 64 + q * 16));
        const void* s = g + (size_t)row * rs + q * 8;
        asm volatile("cp.async.cg.shared.global [%0], [%1], 16;"
                     :: "r"(d), "l"(s));
    }
}

#define CP_COMMIT() asm volatile("cp.async.commit_group;" ::: "memory")
#define CP_WAIT2()  asm volatile("cp.async.wait_group 2;" ::: "memory")
#define CP_WAIT1()  asm volatile("cp.async.wait_group 1;" ::: "memory")
#define CP_WAIT0()  asm volatile("cp.async.wait_group 0;" ::: "memory")

// SMEM: 3 stages x 4 tiles (Ah, Al, Bh, Bl) x 8KB = 96KB
#define TILE_B   8192
#define STAGE_B  (4 * TILE_B)
#define NSTAGES  3
#define MMA_SMEM (NSTAGES * STAGE_B)

// ---------------------------------------------------------------------------
// Shared HMMA mainloop: acc[4][4][4] += A(128xK) @ B(128xK)^T with
// 2-way bf16 split (Ah*Bh + Ah*Bl + Al*Bh).  K consumed in chunks of 32.
// 8 warps: warp tile = 64(i) x 32(j); iBase=(wid>>2)*64, jBase=(wid&3)*32.
// ---------------------------------------------------------------------------
__device__ __forceinline__ void mma_mainloop(
    uint32_t sbase,
    const __nv_bfloat16* Ah, const __nv_bfloat16* Al,
    const __nv_bfloat16* Bh, const __nv_bfloat16* Bl,
    int rsA, int rsB, int nch,
    float acc[4][4][4], int tid, int wid, int lane)
{
    const int iBase = (wid >> 2) * 64;
    const int jBase = (wid & 3) * 32;
    const uint32_t lsw  = (uint32_t)(((lane >> 1) & 3) * 16);
    const uint32_t aoff = (uint32_t)((iBase + (lane & 15)) * 64 + (lane >> 4) * 16);
    const uint32_t boff = (uint32_t)((jBase + (lane & 15)) * 64 + (lane >> 4) * 16);

    // Prefetch chunks 0 and 1
    #pragma unroll
    for (int p = 0; p < 2; p++) {
        uint32_t st = sbase + p * STAGE_B;
        int ko = p * 32;
        cp_tile(st + 0 * TILE_B, Ah + ko, rsA, tid);
        cp_tile(st + 1 * TILE_B, Al + ko, rsA, tid);
        cp_tile(st + 2 * TILE_B, Bh + ko, rsB, tid);
        cp_tile(st + 3 * TILE_B, Bl + ko, rsB, tid);
        CP_COMMIT();
    }

    int stage = 0;
    #pragma unroll 1
    for (int c = 0; c < nch; c++) {
        if (c + 2 < nch) {
            int ps = stage + 2; if (ps >= NSTAGES) ps -= NSTAGES;
            uint32_t st = sbase + ps * STAGE_B;
            int ko = (c + 2) * 32;
            cp_tile(st + 0 * TILE_B, Ah + ko, rsA, tid);
            cp_tile(st + 1 * TILE_B, Al + ko, rsA, tid);
            cp_tile(st + 2 * TILE_B, Bh + ko, rsB, tid);
            cp_tile(st + 3 * TILE_B, Bl + ko, rsB, tid);
            CP_COMMIT();
            CP_WAIT2();
        } else if (c + 2 == nch) {
            CP_WAIT1();
        } else {
            CP_WAIT0();
        }
        __syncthreads();

        uint32_t tb = sbase + stage * STAGE_B;
        #pragma unroll
        for (int ks = 0; ks < 2; ks++) {
            uint32_t kb = (uint32_t)(ks * 32);

            uint32_t ah[4][4], al[4][4];
            #pragma unroll
            for (int it = 0; it < 4; it++) {
                uint32_t o = (aoff + it * 1024 + kb) ^ lsw;
                ldmx4(ah[it], tb + o);
                ldmx4(al[it], tb + TILE_B + o);
            }
            uint32_t bh[4][2], bl[4][2];
            #pragma unroll
            for (int jp = 0; jp < 2; jp++) {
                uint32_t o = (boff + jp * 1024 + kb) ^ lsw;
                uint32_t t4[4];
                ldmx4(t4, tb + 2 * TILE_B + o);
                bh[jp * 2][0]     = t4[0]; bh[jp * 2][1]     = t4[2];
                bh[jp * 2 + 1][0] = t4[1]; bh[jp * 2 + 1][1] = t4[3];
                ldmx4(t4, tb + 3 * TILE_B + o);
                bl[jp * 2][0]     = t4[0]; bl[jp * 2][1]     = t4[2];
                bl[jp * 2 + 1][0] = t4[1]; bl[jp * 2 + 1][1] = t4[3];
            }

            #pragma unroll
            for (int it = 0; it < 4; it++)
                #pragma unroll
                for (int nt = 0; nt < 4; nt++) {
                    mma16816(acc[it][nt], ah[it], bh[nt][0], bh[nt][1]);
                    mma16816(acc[it][nt], ah[it], bl[nt][0], bl[nt][1]);
                    mma16816(acc[it][nt], al[it], bh[nt][0], bh[nt][1]);
                }
        }
        __syncthreads();

        if (++stage == NSTAGES) stage = 0;
    }
}

// ---------------------------------------------------------------------------
// Kernel 1: 1x1 conv projection (SIMT fp32) -> bf16 hi/lo split outputs.
// vmode=0: out [N, C] (q, k).  vmode=1: out [C, N] (v).
// ---------------------------------------------------------------------------
__device__ __forceinline__ void store8_bf16_split(__nv_bfloat16* dh,
                                                  __nv_bfloat16* dl,
                                                  const float* f) {
    uint4 uh, ul;
    __nv_bfloat162* ph = reinterpret_cast<__nv_bfloat162*>(&uh);
    __nv_bfloat162* pl = reinterpret_cast<__nv_bfloat162*>(&ul);
    #pragma unroll
    for (int k = 0; k < 4; k++) {
        float a = f[2 * k], b = f[2 * k + 1];
        __nv_bfloat16 ah = __float2bfloat16_rn(a);
        __nv_bfloat16 bh = __float2bfloat16_rn(b);
        float al = a - __bfloat162float(ah);
        float bl = b - __bfloat162float(bh);
        ph[k] = __halves2bfloat162(ah, bh);
        pl[k] = __halves2bfloat162(__float2bfloat16_rn(al), __float2bfloat16_rn(bl));
    }
    *reinterpret_cast<uint4*>(dh) = uh;
    *reinterpret_cast<uint4*>(dl) = ul;
}

__global__ void __launch_bounds__(256, 2)
proj_kernel(const float* __restrict__ x,
            const float* __restrict__ W,
            const float* __restrict__ bias,
            __nv_bfloat16* __restrict__ oh,
            __nv_bfloat16* __restrict__ ol,
            int vmode) {
    __shared__ __align__(16) float As[16][128];   // As[cc][nn]
    __shared__ __align__(16) float Bs[16][132];   // Bs[cc][oo]

    const int b  = blockIdx.z;
    const int o0 = blockIdx.y * 128;
    const int n0 = blockIdx.x * 128;
    const int tid = threadIdx.x;
    const int tx = tid & 15, ty = tid >> 4;

    const float* xb = x + (size_t)b * Cn * Nn;

    float acc[8][8] = {};

    for (int c0 = 0; c0 < Cn; c0 += 16) {
        #pragma unroll
        for (int k = 0; k < 2; k++) {
            int p = tid + k * 256;
            int cc = p >> 5, nn4 = (p & 31) * 4;
            *reinterpret_cast<float4*>(&As[cc][nn4]) =
                *reinterpret_cast<const float4*>(&xb[(size_t)(c0 + cc) * Nn + n0 + nn4]);
        }
        #pragma unroll
        for (int k = 0; k < 2; k++) {
            int p = tid + k * 256;
            int oo = p >> 2, c4 = (p & 3) * 4;
            float4 w = *reinterpret_cast<const float4*>(&W[(size_t)(o0 + oo) * Cn + c0 + c4]);
            Bs[c4 + 0][oo] = w.x;
            Bs[c4 + 1][oo] = w.y;
            Bs[c4 + 2][oo] = w.z;
            Bs[c4 + 3][oo] = w.w;
        }
        __syncthreads();

        #pragma unroll
        for (int cc = 0; cc < 16; cc++) {
            float4 a0 = *reinterpret_cast<const float4*>(&As[cc][ty * 8]);
            float4 a1 = *reinterpret_cast<const float4*>(&As[cc][ty * 8 + 4]);
            float4 b0 = *reinterpret_cast<const float4*>(&Bs[cc][tx * 8]);
            float4 b1 = *reinterpret_cast<const float4*>(&Bs[cc][tx * 8 + 4]);
            float a[8] = {a0.x, a0.y, a0.z, a0.w, a1.x, a1.y, a1.z, a1.w};
            float bb[8] = {b0.x, b0.y, b0.z, b0.w, b1.x, b1.y, b1.z, b1.w};
            #pragma unroll
            for (int i = 0; i < 8; i++)
                #pragma unroll
                for (int j = 0; j < 8; j++)
                    acc[i][j] += a[i] * bb[j];
        }
        __syncthreads();
    }

    float bj[8];
    #pragma unroll
    for (int j = 0; j < 8; j++) bj[j] = bias[o0 + tx * 8 + j];

    if (!vmode) {
        __nv_bfloat16* dh = oh + (size_t)b * Nn * Cn;
        __nv_bfloat16* dl = ol + (size_t)b * Nn * Cn;
        #pragma unroll
        for (int i = 0; i < 8; i++) {
            float f[8];
            #pragma unroll
            for (int j = 0; j < 8; j++) f[j] = acc[i][j] + bj[j];
            size_t base = (size_t)(n0 + ty * 8 + i) * Cn + o0 + tx * 8;
            store8_bf16_split(dh + base, dl + base, f);
        }
    } else {
        __nv_bfloat16* dh = oh + (size_t)b * Cn * Nn;
        __nv_bfloat16* dl = ol + (size_t)b * Cn * Nn;
        #pragma unroll
        for (int j = 0; j < 8; j++) {
            float f[8];
            #pragma unroll
            for (int i = 0; i < 8; i++) f[i] = acc[i][j] + bj[j];
            size_t base = (size_t)(o0 + tx * 8 + j) * Nn + n0 + ty * 8;
            store8_bf16_split(dh + base, dl + base, f);
        }
    }
}

// ---------------------------------------------------------------------------
// Kernel 2: scores via HMMA.  S[b,i,j] = mask[b,i] * <q_i, k_j>
// ---------------------------------------------------------------------------
__global__ void __launch_bounds__(256, 2)
scores_mma(const float* __restrict__ mask) {
    extern __shared__ char smem[];
    uint32_t sbase = smem_u32(smem);
    const int tid = threadIdx.x;
    const int wid = tid >> 5, lane = tid & 31;

    const int b  = blockIdx.z;
    const int i0 = blockIdx.y * 128;
    const int j0 = blockIdx.x * 128;

    const __nv_bfloat16* Ah = g_qh + ((size_t)b * Nn + i0) * Cn;
    const __nv_bfloat16* Al = g_ql + ((size_t)b * Nn + i0) * Cn;
    const __nv_bfloat16* Bh = g_kh + ((size_t)b * Nn + j0) * Cn;
    const __nv_bfloat16* Bl = g_kl + ((size_t)b * Nn + j0) * Cn;

    float acc[4][4][4] = {};
    mma_mainloop(sbase, Ah, Al, Bh, Bl, Cn, Cn, Cn / 32, acc, tid, wid, lane);

    // Epilogue
    const int iBase = (wid >> 2) * 64;
    const int jBase = (wid & 3) * 32;
    const int g = lane >> 2, cp2 = (lane & 3) * 2;
    const float* mb = mask + (size_t)b * Nn;
    float* Sb = g_S + (size_t)b * Nn * Nn;

    #pragma unroll
    for (int it = 0; it < 4; it++) {
        int r1 = i0 + iBase + it * 16 + g;
        float m1 = mb[r1], m2 = mb[r1 + 8];
        #pragma unroll
        for (int nt = 0; nt < 4; nt++) {
            int cc = j0 + jBase + nt * 8 + cp2;
            float2 v1 = {acc[it][nt][0] * m1, acc[it][nt][1] * m1};
            float2 v2 = {acc[it][nt][2] * m2, acc[it][nt][3] * m2};
            *reinterpret_cast<float2*>(&Sb[(size_t)r1 * Nn + cc])       = v1;
            *reinterpret_cast<float2*>(&Sb[(size_t)(r1 + 8) * Nn + cc]) = v2;
        }
    }
}

// ---------------------------------------------------------------------------
// Kernel 3: row softmax over S; writes P as bf16 hi/lo.
// ---------------------------------------------------------------------------
__global__ void softmax_kernel() {
    const size_t row = blockIdx.x;
    const float* src = g_S + row * Nn;
    __nv_bfloat16* dh = g_Ph + row * Nn;
    __nv_bfloat16* dl = g_Pl + row * Nn;

    const int tid  = threadIdx.x;
    const int warp = tid >> 5;
    const int lane = tid & 31;

    __shared__ float sred[8];
    __shared__ float sbcast;

    float2 v[8];
    float mx = -1e30f;
    #pragma unroll
    for (int t = 0; t < 8; t++) {
        v[t] = *reinterpret_cast<const float2*>(&src[t * 512 + tid * 2]);
        mx = fmaxf(mx, fmaxf(v[t].x, v[t].y));
    }
    #pragma unroll
    for (int o = 16; o > 0; o >>= 1)
        mx = fmaxf(mx, __shfl_xor_sync(0xffffffffu, mx, o));
    if (lane == 0) sred[warp] = mx;
    __syncthreads();
    if (warp == 0) {
        float x = sred[lane & 7];
        #pragma unroll
        for (int o = 4; o > 0; o >>= 1)
            x = fmaxf(x, __shfl_xor_sync(0xffffffffu, x, o));
        if (lane == 0) sbcast = x;
    }
    __syncthreads();
    mx = sbcast;

    float s = 0.f;
    #pragma unroll
    for (int t = 0; t < 8; t++) {
        v[t].x = __expf(v[t].x - mx);
        v[t].y = __expf(v[t].y - mx);
        s += v[t].x + v[t].y;
    }
    #pragma unroll
    for (int o = 16; o > 0; o >>= 1)
        s += __shfl_xor_sync(0xffffffffu, s, o);
    __syncthreads();
    if (lane == 0) sred[warp] = s;
    __syncthreads();
    if (warp == 0) {
        float x = sred[lane & 7];
        #pragma unroll
        for (int o = 4; o > 0; o >>= 1)
            x += __shfl_xor_sync(0xffffffffu, x, o);
        if (lane == 0) sbcast = x;
    }
    __syncthreads();
    const float inv = 1.f / sbcast;

    #pragma unroll
    for (int t = 0; t < 8; t++) {
        float a = v[t].x * inv, b = v[t].y * inv;
        __nv_bfloat16 ah = __float2bfloat16_rn(a);
        __nv_bfloat16 bh = __float2bfloat16_rn(b);
        float al = a - __bfloat162float(ah);
        float bl = b - __bfloat162float(bh);
        int off = t * 512 + tid * 2;
        *reinterpret_cast<__nv_bfloat162*>(&dh[off]) = __halves2bfloat162(ah, bh);
        *reinterpret_cast<__nv_bfloat162*>(&dl[off]) =
            __halves2bfloat162(__float2bfloat16_rn(al), __float2bfloat16_rn(bl));
    }
}

// ---------------------------------------------------------------------------
// Kernel 4: PV via HMMA (computes D^T: rows = c, cols = q) + final blend.
// D[c][q] = sum_j v[c][j] * P[q][j];  out[b,c,q] = queries*m + (1-m)*D
// ---------------------------------------------------------------------------
__global__ void __launch_bounds__(256, 2)
pv_mma(const float* __restrict__ mask,
       const float* __restrict__ queries,
       float* __restrict__ out) {
    extern __shared__ char smem[];
    uint32_t sbase = smem_u32(smem);
    const int tid = threadIdx.x;
    const int wid = tid >> 5, lane = tid & 31;

    const int b  = blockIdx.z;
    const int c0 = blockIdx.y * 128;
    const int q0 = blockIdx.x * 128;

    const __nv_bfloat16* Ah = g_vh + ((size_t)b * Cn + c0) * Nn;
    const __nv_bfloat16* Al = g_vl + ((size_t)b * Cn + c0) * Nn;
    const __nv_bfloat16* Bh = g_Ph + ((size_t)b * Nn + q0) * Nn;
    const __nv_bfloat16* Bl = g_Pl + ((size_t)b * Nn + q0) * Nn;

    float acc[4][4][4] = {};
    mma_mainloop(sbase, Ah, Al, Bh, Bl, Nn, Nn, Nn / 32, acc, tid, wid, lane);

    // Epilogue: rows = c, cols = q (contiguous in output)
    const int iBase = (wid >> 2) * 64;
    const int jBase = (wid & 3) * 32;
    const int g = lane >> 2, cp2 = (lane & 3) * 2;
    const float* mb = mask + (size_t)b * Nn;

    int   qc[4];
    float m0[4], m1[4];
    #pragma unroll
    for (int nt = 0; nt < 4; nt++) {
        qc[nt] = q0 + jBase + nt * 8 + cp2;
        m0[nt] = mb[qc[nt]];
        m1[nt] = mb[qc[nt] + 1];
    }

    #pragma unroll
    for (int it = 0; it < 4; it++) {
        int cr = c0 + iBase + it * 16 + g;
        #pragma unroll
        for (int nt = 0; nt < 4; nt++) {
            size_t gi1 = ((size_t)b * Cn + cr) * Nn + qc[nt];
            size_t gi2 = gi1 + (size_t)8 * Nn;
            float2 qa = *reinterpret_cast<const float2*>(&queries[gi1]);
            float2 qb = *reinterpret_cast<const float2*>(&queries[gi2]);
            float2 o1, o2;
            o1.x = qa.x * m0[nt] + (1.f - m0[nt]) * acc[it][nt][0];
            o1.y = qa.y * m1[nt] + (1.f - m1[nt]) * acc[it][nt][1];
            o2.x = qb.x * m0[nt] + (1.f - m0[nt]) * acc[it][nt][2];
            o2.y = qb.y * m1[nt] + (1.f - m1[nt]) * acc[it][nt][3];
            *reinterpret_cast<float2*>(&out[gi1]) = o1;
            *reinterpret_cast<float2*>(&out[gi2]) = o2;
        }
    }
}

// ---------------------------------------------------------------------------
// Launch
// ---------------------------------------------------------------------------
extern "C" void kernel_launch(void* const* d_in, const int* in_sizes, int n_in,
                              void* d_out, int out_size) {
    const float* queries = (const float*)d_in[0];
    const float* keys    = (const float*)d_in[1];
    const float* mask    = (const float*)d_in[2];
    const float* Wq      = (const float*)d_in[3];
    const float* bq      = (const float*)d_in[4];
    const float* Wk      = (const float*)d_in[5];
    const float* bk      = (const float*)d_in[6];
    const float* Wv      = (const float*)d_in[7];
    const float* bv      = (const float*)d_in[8];
    float* out = (float*)d_out;

    cudaFuncSetAttribute(scores_mma, cudaFuncAttributeMaxDynamicSharedMemorySize,
                         MMA_SMEM);
    cudaFuncSetAttribute(pv_mma, cudaFuncAttributeMaxDynamicSharedMemorySize,
                         MMA_SMEM);

    __nv_bfloat16 *qh, *ql, *kh, *kl, *vh, *vl;
    cudaGetSymbolAddress((void**)&qh, g_qh);
    cudaGetSymbolAddress((void**)&ql, g_ql);
    cudaGetSymbolAddress((void**)&kh, g_kh);
    cudaGetSymbolAddress((void**)&kl, g_kl);
    cudaGetSymbolAddress((void**)&vh, g_vh);
    cudaGetSymbolAddress((void**)&vl, g_vl);

    // Projections (SIMT fp32 -> bf16 hi/lo split outputs)
    dim3 gproj(Nn / 128, Cn / 128, Bn);
    proj_kernel<<<gproj, 256>>>(queries, Wq, bq, qh, ql, 0);
    proj_kernel<<<gproj, 256>>>(keys,    Wk, bk, kh, kl, 0);
    proj_kernel<<<gproj, 256>>>(keys,    Wv, bv, vh, vl, 1);

    // Scores (HMMA, 3-product bf16 split) + mask
    dim3 gsc(Nn / 128, Nn / 128, Bn);
    scores_mma<<<gsc, 256, MMA_SMEM>>>(mask);

    // Row softmax -> P hi/lo
    softmax_kernel<<<Bn * Nn, 256>>>();

    // PV (HMMA, computes D^T) + final blend
    dim3 gpv(Nn / 128, Cn / 128, Bn);
    pv_mma<<<gpv, 256, MMA_SMEM>>>(mask, queries, out);
}